// round 16
// baseline (speedup 1.0000x reference)
#include <cuda_runtime.h>
#include <cuda_fp16.h>
#include <math.h>
#include <stdint.h>

// ---------------------------------------------------------------------------
// Problem constants
// ---------------------------------------------------------------------------
#define BQ    8
#define MTOT  32768
#define CDIM  512
#define TDIM  768
#define KTXT  128
#define HID   2048
#define TOPM  5
#define TEMP_INV (1.0f/0.07f)
#define LN_EPS 1e-5f
#define WSCALE 256.0f
#define WINV   (1.0f/256.0f)

// ---------------------------------------------------------------------------
// Scratch (device globals)
// ---------------------------------------------------------------------------
static __device__ uint32_t g_vh[MTOT * CDIM / 2];
static __device__ uint32_t g_vl[MTOT * CDIM / 2];
static __device__ float    g_X [MTOT * CDIM];
static __device__ uint32_t g_Xh[MTOT * CDIM / 2];
static __device__ uint32_t g_Hh[(size_t)MTOT * HID / 2];
static __device__ float    g_sim[(size_t)MTOT * KTXT];
static __device__ float    g_keyt [BQ * KTXT * TDIM];
static __device__ float    g_value[BQ * KTXT * CDIM];
static __device__ float    g_P [BQ * CDIM * KTXT];
static __device__ float    g_G [CDIM * CDIM];
static __device__ uint32_t g_Gh [CDIM * CDIM / 2];
static __device__ uint32_t g_Gl [CDIM * CDIM / 2];
static __device__ uint32_t g_Ph [BQ * KTXT * CDIM / 2];
static __device__ uint32_t g_Pl [BQ * KTXT * CDIM / 2];
static __device__ uint32_t g_W1h[(size_t)HID * CDIM / 2];
static __device__ uint32_t g_W1l[(size_t)HID * CDIM / 2];
static __device__ uint32_t g_W2h[(size_t)CDIM * HID / 2];
static __device__ uint32_t g_W2l[(size_t)CDIM * HID / 2];
static __device__ float    g_pb [BQ * KTXT];
static __device__ float    g_wb2[CDIM];
static __device__ float    g_nb2[1];
static __device__ float    g_qn2[MTOT];

// ---------------------------------------------------------------------------
// Helpers
// ---------------------------------------------------------------------------
__device__ __forceinline__ uint32_t packh2(float x, float y) {
    __half2 h = __floats2half2_rn(x, y);
    return *reinterpret_cast<uint32_t*>(&h);
}

__device__ __forceinline__ void wsplit2(float x, float y,
                                        uint32_t& hi, uint32_t& lo) {
    float sx = x * WSCALE, sy = y * WSCALE;
    __half hx = __float2half_rn(sx);
    __half hy = __float2half_rn(sy);
    float rx = sx - __half2float(hx);
    float ry = sy - __half2float(hy);
    __half2 h2 = __halves2half2(hx, hy);
    __half2 l2 = __floats2half2_rn(rx, ry);
    hi = *reinterpret_cast<uint32_t*>(&h2);
    lo = *reinterpret_cast<uint32_t*>(&l2);
}

__device__ __forceinline__ void asplit2(float x, float y,
                                        uint32_t& hi, uint32_t& lo) {
    __half hx = __float2half_rn(x);
    __half hy = __float2half_rn(y);
    float rx = x - __half2float(hx);
    float ry = y - __half2float(hy);
    __half2 h2 = __halves2half2(hx, hy);
    __half2 l2 = __floats2half2_rn(rx, ry);
    hi = *reinterpret_cast<uint32_t*>(&h2);
    lo = *reinterpret_cast<uint32_t*>(&l2);
}

__device__ __forceinline__ void mma_f16(float* c, const uint32_t* a, const uint32_t* b) {
    asm volatile(
        "mma.sync.aligned.m16n8k16.row.col.f32.f16.f16.f32 "
        "{%0,%1,%2,%3}, {%4,%5,%6,%7}, {%8,%9}, {%0,%1,%2,%3};\n"
        : "+f"(c[0]), "+f"(c[1]), "+f"(c[2]), "+f"(c[3])
        : "r"(a[0]), "r"(a[1]), "r"(a[2]), "r"(a[3]), "r"(b[0]), "r"(b[1]));
}

__device__ __forceinline__ uint32_t smem_u32(const void* p) {
    uint32_t a;
    asm("{ .reg .u64 t; cvta.to.shared.u64 t, %1; cvt.u32.u64 %0, t; }"
        : "=r"(a) : "l"(p));
    return a;
}

__device__ __forceinline__ void ldsm_x4(uint32_t& r0, uint32_t& r1,
                                        uint32_t& r2, uint32_t& r3,
                                        uint32_t addr) {
    asm volatile(
        "ldmatrix.sync.aligned.m8n8.x4.shared.b16 {%0,%1,%2,%3}, [%4];"
        : "=r"(r0), "=r"(r1), "=r"(r2), "=r"(r3) : "r"(addr));
}

__device__ __forceinline__ void cp16(uint32_t* dst_smem, const uint32_t* src) {
    uint32_t s = (uint32_t)__cvta_generic_to_shared(dst_smem);
    asm volatile("cp.async.cg.shared.global [%0], [%1], 16;\n" :: "r"(s), "l"(src));
}
__device__ __forceinline__ void cp_commit() {
    asm volatile("cp.async.commit_group;\n");
}
__device__ __forceinline__ void cp_wait1() {
    asm volatile("cp.async.wait_group 1;\n");
}

// ---------------------------------------------------------------------------
// Device bodies (math identical to R15)
// ---------------------------------------------------------------------------
__device__ void ln_body(const float* __restrict__ in, const float* __restrict__ g,
                        const float* __restrict__ be,
                        uint32_t* __restrict__ oh, uint32_t* __restrict__ ol, int blk)
{
    int warp = threadIdx.x >> 5, lane = threadIdx.x & 31;
    size_t row = (size_t)blk * 8 + warp;
    const float4* p = (const float4*)(in + row * CDIM);
    float4 x[4];
    float s = 0.f, s2 = 0.f;
    #pragma unroll
    for (int i = 0; i < 4; i++) {
        x[i] = p[lane + 32 * i];
        s  += x[i].x + x[i].y + x[i].z + x[i].w;
        s2 += x[i].x * x[i].x + x[i].y * x[i].y + x[i].z * x[i].z + x[i].w * x[i].w;
    }
    #pragma unroll
    for (int o = 16; o; o >>= 1) {
        s  += __shfl_xor_sync(0xffffffffu, s, o);
        s2 += __shfl_xor_sync(0xffffffffu, s2, o);
    }
    float mu  = s * (1.0f / CDIM);
    float var = s2 * (1.0f / CDIM) - mu * mu;
    float rs  = rsqrtf(var + LN_EPS);
    const float4* gp = (const float4*)g;
    const float4* bp = (const float4*)be;
    #pragma unroll
    for (int i = 0; i < 4; i++) {
        int c4 = lane + 32 * i;
        float4 gv = gp[c4], bv = bp[c4], r;
        r.x = (x[i].x - mu) * rs * gv.x + bv.x;
        r.y = (x[i].y - mu) * rs * gv.y + bv.y;
        r.z = (x[i].z - mu) * rs * gv.z + bv.z;
        r.w = (x[i].w - mu) * rs * gv.w + bv.w;
        uint2 h, l;
        asplit2(r.x, r.y, h.x, l.x);
        asplit2(r.z, r.w, h.y, l.y);
        *(uint2*)(oh + row * (CDIM / 2) + 2 * c4) = h;
        *(uint2*)(ol + row * (CDIM / 2) + 2 * c4) = l;
    }
}

__device__ void prep_text_body(const float* __restrict__ text,
                               const float* __restrict__ Wv,
                               const float* __restrict__ bv,
                               float (*ts)[TDIM], int blk)
{
    int tid = threadIdx.x, lane = tid & 31, warp = tid >> 5;
    int b  = blk >> 4;
    int kb = (blk & 15) * 8;
    const float* tb = text + ((size_t)b * KTXT + kb) * TDIM;

    #pragma unroll
    for (int i = 0; i < 24; i++) {
        int lin = tid + 256 * i;
        int r = lin / TDIM, c = lin % TDIM;
        ts[r][c] = tb[(size_t)r * TDIM + c];
    }
    __syncthreads();

    {
        int r = warp;
        float s = 0.f;
        for (int i = lane; i < TDIM; i += 32) { float v = ts[r][i]; s += v * v; }
        #pragma unroll
        for (int o = 16; o; o >>= 1) s += __shfl_xor_sync(0xffffffffu, s, o);
        float inv = 1.0f / fmaxf(sqrtf(s), 1e-12f);
        float* kr = g_keyt + ((size_t)b * KTXT + kb + r) * TDIM;
        for (int i = lane; i < TDIM; i += 32) kr[i] = ts[r][i] * inv;
    }

    float acc[8][2];
    #pragma unroll
    for (int r = 0; r < 8; r++) { acc[r][0] = 0.f; acc[r][1] = 0.f; }
    int c0 = tid, c1 = tid + 256;
    for (int t = 0; t < TDIM; t++) {
        float w0 = Wv[(size_t)t * CDIM + c0];
        float w1 = Wv[(size_t)t * CDIM + c1];
        #pragma unroll
        for (int r = 0; r < 8; r++) {
            float tv = ts[r][t];
            acc[r][0] += tv * w0;
            acc[r][1] += tv * w1;
        }
    }
    float bb0 = bv[c0], bb1 = bv[c1];
    #pragma unroll
    for (int r = 0; r < 8; r++) {
        float* vr = g_value + ((size_t)b * KTXT + kb + r) * CDIM;
        vr[c0] = acc[r][0] + bb0;
        vr[c1] = acc[r][1] + bb1;
    }
}

__device__ void convert_body(const float* __restrict__ in,
                             uint32_t* __restrict__ oh, uint32_t* __restrict__ ol,
                             int Kd, int N, int bx, int by, int bz,
                             size_t inStride, size_t outStride, float (*t)[65])
{
    int k0 = by * 64, n0 = bx * 64;
    const float* inb = in + (size_t)bz * inStride;
    int tid = threadIdx.x;
    #pragma unroll
    for (int i = 0; i < 16; i++) {
        int lin = tid + 256 * i;
        int r = lin >> 6, c = lin & 63;
        t[r][c] = inb[(size_t)(k0 + r) * N + n0 + c];
    }
    __syncthreads();
    int K2 = Kd >> 1;
    #pragma unroll
    for (int i = 0; i < 8; i++) {
        int lin = tid + 256 * i;
        int n = lin >> 5, kp = lin & 31;
        uint32_t h, l;
        wsplit2(t[2 * kp][n], t[2 * kp + 1][n], h, l);
        size_t o = (size_t)bz * outStride + (size_t)(n0 + n) * K2 + (k0 >> 1) + kp;
        oh[o] = h;  ol[o] = l;
    }
}

__device__ void wb2_body(const float* __restrict__ Wq,
                         const float* __restrict__ bq, int gw2)
{
    if (gw2 > 512) return;
    int lane = threadIdx.x & 31;
    const float4* bp = (const float4*)bq;
    float s = 0.f;
    if (gw2 < 512) {
        const float4* wr = (const float4*)(Wq + (size_t)gw2 * TDIM);
        #pragma unroll
        for (int i = 0; i < 6; i++) {
            float4 a = wr[lane + 32 * i], d = bp[lane + 32 * i];
            s += a.x * d.x + a.y * d.y + a.z * d.z + a.w * d.w;
        }
        #pragma unroll
        for (int o = 16; o; o >>= 1) s += __shfl_xor_sync(0xffffffffu, s, o);
        if (!lane) g_wb2[gw2] = 2.0f * s;
    } else {
        #pragma unroll
        for (int i = 0; i < 6; i++) {
            float4 a = bp[lane + 32 * i];
            s += a.x * a.x + a.y * a.y + a.z * a.z + a.w * a.w;
        }
        #pragma unroll
        for (int o = 16; o; o >>= 1) s += __shfl_xor_sync(0xffffffffu, s, o);
        if (!lane) g_nb2[0] = s;
    }
}

__device__ void pb_body(const float* __restrict__ bq, int gw)
{
    if (gw >= 1024) return;
    int lane = threadIdx.x & 31;
    const float4* bp = (const float4*)bq;
    const float4* kr = (const float4*)(g_keyt + (size_t)gw * TDIM);
    float s = 0.f;
    #pragma unroll
    for (int i = 0; i < 6; i++) {
        float4 a = kr[lane + 32 * i], c = bp[lane + 32 * i];
        s += a.x * c.x + a.y * c.y + a.z * c.z + a.w * c.w;
    }
    #pragma unroll
    for (int o = 16; o; o >>= 1) s += __shfl_xor_sync(0xffffffffu, s, o);
    if (!lane) g_pb[gw] = s;
}

__device__ void sgemm_body(const float* __restrict__ A, const float* __restrict__ B2,
                           float* __restrict__ C, int Kd, int N, int bn, int bm,
                           float (*As)[128], float (*Bs)[128])
{
    int tid = threadIdx.x;
    int tx = tid & 15, ty = tid >> 4;
    const float* Ab = A  + (size_t)bm * 128 * Kd;
    const float* Bb = B2 + (size_t)bn * 128 * Kd;
    int l_r = tid >> 1, l_k = (tid & 1) * 4;

    float acc[8][8];
    #pragma unroll
    for (int i = 0; i < 8; i++)
        #pragma unroll
        for (int j = 0; j < 8; j++) acc[i][j] = 0.f;

    for (int k0 = 0; k0 < Kd; k0 += 8) {
        float4 av = *(const float4*)(Ab + (size_t)l_r * Kd + k0 + l_k);
        As[l_k + 0][l_r] = av.x;
        As[l_k + 1][l_r] = av.y;
        As[l_k + 2][l_r] = av.z;
        As[l_k + 3][l_r] = av.w;
        float4 bv = *(const float4*)(Bb + (size_t)l_r * Kd + k0 + l_k);
        Bs[l_k + 0][l_r] = bv.x;
        Bs[l_k + 1][l_r] = bv.y;
        Bs[l_k + 2][l_r] = bv.z;
        Bs[l_k + 3][l_r] = bv.w;
        __syncthreads();
        #pragma unroll
        for (int k = 0; k < 8; k++) {
            float ar[8], br[8];
            #pragma unroll
            for (int i = 0; i < 4; i++) {
                ar[i]     = As[k][ty * 4 + i];
                ar[4 + i] = As[k][64 + ty * 4 + i];
                br[i]     = Bs[k][tx * 4 + i];
                br[4 + i] = Bs[k][64 + tx * 4 + i];
            }
            #pragma unroll
            for (int i = 0; i < 8; i++)
                #pragma unroll
                for (int j = 0; j < 8; j++) acc[i][j] += ar[i] * br[j];
        }
        __syncthreads();
    }

    #pragma unroll
    for (int gi = 0; gi < 2; gi++)
        #pragma unroll
        for (int ii = 0; ii < 4; ii++) {
            int r = bm * 128 + gi * 64 + ty * 4 + ii;
            #pragma unroll
            for (int gj = 0; gj < 2; gj++) {
                int cb = bn * 128 + gj * 64 + tx * 4;
                float4 o;
                o.x = acc[gi * 4 + ii][gj * 4 + 0];
                o.y = acc[gi * 4 + ii][gj * 4 + 1];
                o.z = acc[gi * 4 + ii][gj * 4 + 2];
                o.w = acc[gi * 4 + ii][gj * 4 + 3];
                *(float4*)(C + (size_t)r * N + cb) = o;
            }
        }
}

// ---------------------------------------------------------------------------
// fp16 tensor-core GEMM body: 3-stage cp.async pipeline, ONE barrier per tile.
// Iter t: wait1 -> sync -> compute buf t%3 -> stage tile t+2 into (t+2)%3
// ((t+2)%3 == (t-1)%3 was last read at iter t-1; this iter's sync protects it)
// ---------------------------------------------------------------------------
#define A_PLANE 5120
#define B_PLANE 2560

template <int MODE, int AP, int BP>
__device__ void tg_body(
    const uint32_t* __restrict__ Ah, const uint32_t* __restrict__ Al,
    const uint32_t* __restrict__ Bh, const uint32_t* __restrict__ Bl,
    const float* __restrict__ bias, const float* __restrict__ Res,
    float* __restrict__ Out, uint32_t* __restrict__ Oh,
    int M, int N, int Kd, int bn, int bm, uint32_t* sm)
{
    const int STG = AP * A_PLANE + BP * B_PLANE;
    uint32_t sbase = smem_u32(sm);
    int K2 = Kd >> 1;
    int tid = threadIdx.x, lane = tid & 31, warp = tid >> 5;
    int g  = lane >> 2, tg = lane & 3;
    int wm = warp >> 2, wn = warp & 3;
    int m0 = wm * 64,  n0 = wn * 32;

    const uint32_t* AhB = Ah + (size_t)bm * 256 * K2;
    const uint32_t* AlB = (AP == 2) ? Al + (size_t)bm * 256 * K2 : nullptr;
    size_t bofs = (size_t)bn * 128 * K2;
    if (MODE == 0) bofs += (size_t)(bm >> 4) * KTXT * K2;
    const uint32_t* BhB = Bh + bofs;
    const uint32_t* BlB = (BP == 2) ? Bl + bofs : nullptr;

    uint32_t a_ld = (uint32_t)((m0 + (lane & 7) + ((lane >> 3) & 1) * 8) * 20
                               + ((lane >> 4) & 1) * 4) * 4;
    uint32_t b_ld = (uint32_t)((n0 + (lane & 7) + ((lane >> 4) & 1) * 8) * 20
                               + ((lane >> 3) & 1) * 4) * 4;

    float acc[4][4][4];
    #pragma unroll
    for (int mi = 0; mi < 4; mi++)
        #pragma unroll
        for (int ni = 0; ni < 4; ni++)
            #pragma unroll
            for (int r = 0; r < 4; r++) acc[mi][ni][r] = 0.f;

    int nT = K2 / 16;
    const int AOFF = AP * A_PLANE;

    // loader indices
    int arow0 = tid >> 2, akb = (tid & 3) * 4;

    // prologue: stage tiles 0 and 1 (into buffers 0 and 1)
    #pragma unroll
    for (int pf = 0; pf < 2; pf++) {
        uint32_t* st = sm + pf * STG;
        int kp0 = pf * 16;
        #pragma unroll
        for (int c = 0; c < 2; c++) {
            int idx = tid + 512 * c;
            int row = idx >> 2, kb = (idx & 3) * 4;
            size_t go = (size_t)row * K2 + kp0 + kb;
            cp16(st + row * 20 + kb, AhB + go);
            if (AP == 2) cp16(st + A_PLANE + row * 20 + kb, AlB + go);
        }
        {
            size_t go = (size_t)arow0 * K2 + kp0 + akb;
            int so = arow0 * 20 + akb;
            cp16(st + AOFF + so, BhB + go);
            if (BP == 2) cp16(st + AOFF + B_PLANE + so, BlB + go);
        }
        cp_commit();
    }

    int rd = 0, wr = 2;   // rotating buffer indices: read = t%3, write = (t+2)%3
    for (int t = 0; t < nT; t++) {
        cp_wait1();
        __syncthreads();
        uint32_t stb = sbase + (uint32_t)(rd * STG * 4);

        #pragma unroll
        for (int ks = 0; ks < 2; ks++) {
            uint32_t ksoff = (uint32_t)(ks * 32);
            uint32_t a[4][4], al[4][4], bh[4][2], bl[4][2];
            #pragma unroll
            for (int mi = 0; mi < 4; mi++) {
                uint32_t ao = stb + a_ld + ksoff + (uint32_t)(mi * 16 * 80);
                ldsm_x4(a[mi][0], a[mi][1], a[mi][2], a[mi][3], ao);
                if (AP == 2)
                    ldsm_x4(al[mi][0], al[mi][1], al[mi][2], al[mi][3],
                            ao + A_PLANE * 4);
            }
            #pragma unroll
            for (int p = 0; p < 2; p++) {
                uint32_t bo = stb + AOFF * 4 + b_ld + ksoff + (uint32_t)(p * 16 * 80);
                ldsm_x4(bh[2 * p][0], bh[2 * p][1], bh[2 * p + 1][0], bh[2 * p + 1][1], bo);
                if (BP == 2)
                    ldsm_x4(bl[2 * p][0], bl[2 * p][1], bl[2 * p + 1][0], bl[2 * p + 1][1],
                            bo + B_PLANE * 4);
            }
            #pragma unroll
            for (int mi = 0; mi < 4; mi++)
                #pragma unroll
                for (int ni = 0; ni < 4; ni++) {
                    mma_f16(acc[mi][ni], a[mi], bh[ni]);
                    if (BP == 2) mma_f16(acc[mi][ni], a[mi], bl[ni]);
                    if (AP == 2) mma_f16(acc[mi][ni], al[mi], bh[ni]);
                }
        }

        if (t + 2 < nT) {
            uint32_t* dst = sm + wr * STG;
            int kp0 = (t + 2) * 16;
            #pragma unroll
            for (int c = 0; c < 2; c++) {
                int idx = tid + 512 * c;
                int row = idx >> 2, kb = (idx & 3) * 4;
                size_t go = (size_t)row * K2 + kp0 + kb;
                cp16(dst + row * 20 + kb, AhB + go);
                if (AP == 2) cp16(dst + A_PLANE + row * 20 + kb, AlB + go);
            }
            {
                size_t go = (size_t)arow0 * K2 + kp0 + akb;
                int so = arow0 * 20 + akb;
                cp16(dst + AOFF + so, BhB + go);
                if (BP == 2) cp16(dst + AOFF + B_PLANE + so, BlB + go);
            }
        }
        cp_commit();
        rd = (rd == 2) ? 0 : rd + 1;
        wr = (wr == 2) ? 0 : wr + 1;
    }

    if (MODE == 3) {
        #pragma unroll
        for (int mi = 0; mi < 4; mi++)
            #pragma unroll
            for (int half = 0; half < 2; half++) {
                int r = bm * 256 + m0 + mi * 16 + g + half * 8;
                float part = 0.f;
                #pragma unroll
                for (int ni = 0; ni < 4; ni++) {
                    int c = bn * 128 + n0 + ni * 8 + 2 * tg;
                    uint32_t hu = Ah[(size_t)r * (N >> 1) + (c >> 1)];
                    uint32_t lu = Al[(size_t)r * (N >> 1) + (c >> 1)];
                    __half2 h2 = *reinterpret_cast<__half2*>(&hu);
                    __half2 l2 = *reinterpret_cast<__half2*>(&lu);
                    float h0 = __half2float(__low2half(h2));
                    float h1 = __half2float(__high2half(h2));
                    float l0 = __half2float(__low2half(l2));
                    float l1 = __half2float(__high2half(l2));
                    float z0 = acc[mi][ni][half * 2 + 0] * WINV;
                    float z1 = acc[mi][ni][half * 2 + 1] * WINV;
                    part += z0 * (h0 + 2.0f * l0) + bias[c]     * (h0 + l0);
                    part += z1 * (h1 + 2.0f * l1) + bias[c + 1] * (h1 + l1);
                }
                part += __shfl_xor_sync(0xffffffffu, part, 1);
                part += __shfl_xor_sync(0xffffffffu, part, 2);
                if (tg == 0) atomicAdd(&g_qn2[r], part);
            }
        return;
    }

    #pragma unroll
    for (int mi = 0; mi < 4; mi++)
        #pragma unroll
        for (int half = 0; half < 2; half++) {
            int r = bm * 256 + m0 + mi * 16 + g + half * 8;
            #pragma unroll
            for (int ni = 0; ni < 4; ni++) {
                int c = bn * 128 + n0 + ni * 8 + 2 * tg;
                float v0 = acc[mi][ni][half * 2 + 0] * WINV;
                float v1 = acc[mi][ni][half * 2 + 1] * WINV;
                if (MODE == 0) {
                    float2 ov = { v0, v1 };
                    *(float2*)(Out + (size_t)r * KTXT + c) = ov;
                } else if (MODE == 1) {
                    v0 += bias[c];  v1 += bias[c + 1];
                    v0 = v0 * normcdff(v0);
                    v1 = v1 * normcdff(v1);
                    Oh[(size_t)r * (N >> 1) + (c >> 1)] = packh2(v0, v1);
                } else {
                    v0 += bias[c]     + Res[(size_t)r * N + c];
                    v1 += bias[c + 1] + Res[(size_t)r * N + c + 1];
                    float2 ov = { v0, v1 };
                    *(float2*)(Out + (size_t)r * N + c) = ov;
                }
            }
        }
}

// Thin wrappers for the FFN GEMMs
template <int MODE>
__global__ __launch_bounds__(512) void tgemm4_kernel(
    const uint32_t* __restrict__ Ah,
    const uint32_t* __restrict__ Bh, const uint32_t* __restrict__ Bl,
    const float* __restrict__ bias, const float* __restrict__ Res,
    float* __restrict__ Out, uint32_t* __restrict__ Oh,
    int M, int N, int Kd)
{
    extern __shared__ uint32_t sm[];
    tg_body<MODE, 1, 1>(Ah, nullptr, Bh, Bl, bias, Res, Out, Oh,
                        M, N, Kd, blockIdx.x, blockIdx.y, sm);
}

// Merged sim + qn2 launch: blocks [0,128) sim<0,2,2>, [128,640) qn2<3,1,1>
__global__ __launch_bounds__(512) void fused_simqn2_kernel(
    const float* __restrict__ wb2)
{
    extern __shared__ uint32_t sm[];
    int j = blockIdx.x;
    if (j < 128) {
        tg_body<0, 2, 2>(g_vh, g_vl, g_Ph, g_Pl, nullptr, nullptr,
                         g_sim, nullptr, MTOT, KTXT, CDIM, 0, j, sm);
    } else {
        int jj = j - 128;
        tg_body<3, 1, 1>(g_vh, g_vl, g_Gh, nullptr, wb2, nullptr,
                         nullptr, nullptr, MTOT, CDIM, CDIM,
                         jj >> 7, jj & 127, sm);
    }
}

// ---------------------------------------------------------------------------
// Fused prep launch A
// ---------------------------------------------------------------------------
__global__ __launch_bounds__(256) void fused_prepA_kernel(
    const float* __restrict__ vis, const float* __restrict__ g1,
    const float* __restrict__ be1,
    const float* __restrict__ text, const float* __restrict__ Wv,
    const float* __restrict__ bv,
    const float* __restrict__ W1, const float* __restrict__ W2,
    const float* __restrict__ Wq, const float* __restrict__ bq)
{
    __shared__ __align__(16) char sbuf[24576];
    int j = blockIdx.x;
    if (j < 4096) {
        ln_body(vis, g1, be1, g_vh, g_vl, j);
    } else if (j < 4224) {
        prep_text_body(text, Wv, bv, (float(*)[TDIM])sbuf, j - 4096);
    } else if (j < 4480) {
        int jj = j - 4224;
        convert_body(W1, g_W1h, g_W1l, CDIM, HID, jj & 31, jj >> 5, 0, 0, 0,
                     (float(*)[65])sbuf);
    } else if (j < 4736) {
        int jj = j - 4480;
        convert_body(W2, g_W2h, g_W2l, HID, CDIM, jj & 7, jj >> 3, 0, 0, 0,
                     (float(*)[65])sbuf);
    } else if (j < 4801) {
        int gw2 = (j - 4736) * 8 + (threadIdx.x >> 5);
        wb2_body(Wq, bq, gw2);
    } else {
        int base = (j - 4801) * 2048 + threadIdx.x * 8;
        float4 z = { 0.f, 0.f, 0.f, 0.f };
        *(float4*)(g_qn2 + base)     = z;
        *(float4*)(g_qn2 + base + 4) = z;
    }
}

// ---------------------------------------------------------------------------
// Fused prep launch B: G gemm | P gemms | pb
// ---------------------------------------------------------------------------
__global__ __launch_bounds__(256) void fused_prepB_kernel(
    const float* __restrict__ Wq, const float* __restrict__ bq)
{
    __shared__ __align__(16) float As[8][128];
    __shared__ float Bs[8][128];
    int j = blockIdx.x;
    if (j < 16) {
        sgemm_body(Wq, Wq, g_G, TDIM, CDIM, j & 3, j >> 2, As, Bs);
    } else if (j < 48) {
        int jj = j - 16;
        int bz = jj >> 2, bm = jj & 3;
        sgemm_body(Wq, g_keyt + (size_t)bz * KTXT * TDIM,
                   g_P + (size_t)bz * CDIM * KTXT,
                   TDIM, KTXT, 0, bm, As, Bs);
    } else {
        int gw = (j - 48) * 8 + (threadIdx.x >> 5);
        pb_body(bq, gw);
    }
}

// ---------------------------------------------------------------------------
// Fused prep launch C: convert G | convert P
// ---------------------------------------------------------------------------
__global__ __launch_bounds__(256) void fused_prepC_kernel()
{
    __shared__ __align__(16) float t[64][65];
    int j = blockIdx.x;
    if (j < 64) {
        convert_body(g_G, g_Gh, g_Gl, CDIM, CDIM, j & 7, j >> 3, 0, 0, 0, t);
    } else {
        int jj = j - 64;
        convert_body(g_P, g_Ph, g_Pl, CDIM, KTXT, jj & 1, (jj >> 1) & 7, jj >> 4,
                     (size_t)CDIM * KTXT, (size_t)KTXT * CDIM / 2, t);
    }
}

// ---------------------------------------------------------------------------
// Attention epilogue (unchanged)
// ---------------------------------------------------------------------------
__global__ __launch_bounds__(256) void attn_kernel(
    const float* __restrict__ resid, const float* __restrict__ g2,
    const float* __restrict__ be2)
{
    __shared__ float invn[32];
    __shared__ float pb_s[KTXT];
    int tid = threadIdx.x, lane = tid & 31, warp = tid >> 5;
    int t0 = blockIdx.x * 32;
    int b  = t0 >> 12;

    if (tid < 32) {
        float qn2 = g_qn2[t0 + tid] + g_nb2[0];
        float n = sqrtf(fmaxf(qn2, 0.f));
        invn[tid] = 1.0f / fmaxf(n, 1e-12f);
    }
    if (tid < KTXT) pb_s[tid] = g_pb[b * KTXT + tid];
    __syncthreads();

    for (int rr = 0; rr < 4; rr++) {
        int row = warp * 4 + rr;
        float sc = invn[row];
        const float* sp = g_sim + (size_t)(t0 + row) * KTXT;
        float tv[4];
        #pragma unroll
        for (int j = 0; j < 4; j++) {
            int col = lane + 32 * j;
            tv[j] = (sp[col] + pb_s[col]) * sc;
        }

        float mval[TOPM]; int midx[TOPM];
        #pragma unroll
        for (int it = 0; it < TOPM; it++) {
            float lm = tv[0]; int lj = 0;
            #pragma unroll
            for (int j = 1; j < 4; j++) if (tv[j] > lm) { lm = tv[j]; lj = j; }
            int li = lane + 32 * lj;
            #pragma unroll
            for (int o = 16; o; o >>= 1) {
                float ov = __shfl_xor_sync(0xffffffffu, lm, o);
                int   oi = __shfl_xor_sync(0xffffffffu, li, o);
                if (ov > lm || (ov == lm && oi < li)) { lm = ov; li = oi; }
            }
            mval[it] = lm; midx[it] = li;
            if ((li & 31) == lane) tv[li >> 5] = -INFINITY;
        }

        float p[TOPM], psum = 0.f;
        #pragma unroll
        for (int it = 0; it < TOPM; it++) {
            p[it] = expf((mval[it] - mval[0]) * TEMP_INV);
            psum += p[it];
        }
        float rnorm = 1.0f / psum;

        float f[16];
        #pragma unroll
        for (int i = 0; i < 16; i++) f[i] = 0.f;
        const float* Vb = g_value + (size_t)b * KTXT * CDIM;
        #pragma unroll
        for (int it = 0; it < TOPM; it++) {
            const float4* vr = (const float4*)(Vb + (size_t)midx[it] * CDIM + lane * 16);
            float a_ = p[it] * rnorm;
            #pragma unroll
            for (int j = 0; j < 4; j++) {
                float4 v = vr[j];
                f[4 * j + 0] += a_ * v.x;
                f[4 * j + 1] += a_ * v.y;
                f[4 * j + 2] += a_ * v.z;
                f[4 * j + 3] += a_ * v.w;
            }
        }

        const float4* rp = (const float4*)(resid + (size_t)(t0 + row) * CDIM + lane * 16);
        float s = 0.f, s2 = 0.f;
        #pragma unroll
        for (int j = 0; j < 4; j++) {
            float4 v = rp[j];
            f[4 * j + 0] += v.x;  f[4 * j + 1] += v.y;
            f[4 * j + 2] += v.z;  f[4 * j + 3] += v.w;
        }
        #pragma unroll
        for (int i = 0; i < 16; i++) { s += f[i]; s2 += f[i] * f[i]; }
        #pragma unroll
        for (int o = 16; o; o >>= 1) {
            s  += __shfl_xor_sync(0xffffffffu, s, o);
            s2 += __shfl_xor_sync(0xffffffffu, s2, o);
        }
        float mu  = s * (1.0f / CDIM);
        float var = s2 * (1.0f / CDIM) - mu * mu;
        float rstd = rsqrtf(var + LN_EPS);

        size_t rbase = (size_t)(t0 + row);
        float*    xp = g_X  + rbase * CDIM + lane * 16;
        uint32_t* xh = g_Xh + rbase * (CDIM / 2) + lane * 8;
        #pragma unroll
        for (int j = 0; j < 4; j++) {
            int c = lane * 16 + 4 * j;
            float4 o;
            o.x = (f[4 * j + 0] - mu) * rstd * g2[c + 0] + be2[c + 0];
            o.y = (f[4 * j + 1] - mu) * rstd * g2[c + 1] + be2[c + 1];
            o.z = (f[4 * j + 2] - mu) * rstd * g2[c + 2] + be2[c + 2];
            o.w = (f[4 * j + 3] - mu) * rstd * g2[c + 3] + be2[c + 3];
            *(float4*)(xp + 4 * j) = o;
            uint2 h;
            h.x = packh2(o.x, o.y);
            h.y = packh2(o.z, o.w);
            *(uint2*)(xh + 2 * j) = h;
        }
    }
}

// ---------------------------------------------------------------------------
// Launch
// ---------------------------------------------------------------------------
extern "C" void kernel_launch(void* const* d_in, const int* in_sizes, int n_in,
                              void* d_out, int out_size)
{
    const float* vis  = (const float*)d_in[0];
    const float* text = (const float*)d_in[1];
    const float* Wq   = (const float*)d_in[2];
    const float* bq   = (const float*)d_in[3];
    const float* Wv   = (const float*)d_in[4];
    const float* bv   = (const float*)d_in[5];
    const float* W1   = (const float*)d_in[6];
    const float* b1   = (const float*)d_in[7];
    const float* W2   = (const float*)d_in[8];
    const float* b2   = (const float*)d_in[9];
    const float* g1   = (const float*)d_in[10];
    const float* be1  = (const float*)d_in[11];
    const float* g2   = (const float*)d_in[12];
    const float* be2  = (const float*)d_in[13];
    float* out = (float*)d_out;

    float *p_X, *p_wb2;
    uint32_t *p_Xh, *p_Hh, *p_W1h, *p_W1l, *p_W2h, *p_W2l;
    cudaGetSymbolAddress((void**)&p_X,     g_X);
    cudaGetSymbolAddress((void**)&p_wb2,   g_wb2);
    cudaGetSymbolAddress((void**)&p_Xh,    g_Xh);
    cudaGetSymbolAddress((void**)&p_Hh,    g_Hh);
    cudaGetSymbolAddress((void**)&p_W1h,   g_W1h);
    cudaGetSymbolAddress((void**)&p_W1l,   g_W1l);
    cudaGetSymbolAddress((void**)&p_W2h,   g_W2h);
    cudaGetSymbolAddress((void**)&p_W2l,   g_W2l);

    const int SMEM_1P  = 3 * (1 * A_PLANE + 1 * B_PLANE) * 4;   // 92160
    const int SMEM_SIM = 3 * (2 * A_PLANE + 2 * B_PLANE) * 4;   // 184320
    cudaFuncSetAttribute((const void*)fused_simqn2_kernel,
                         cudaFuncAttributeMaxDynamicSharedMemorySize, SMEM_SIM);
    cudaFuncSetAttribute((const void*)tgemm4_kernel<1>,
                         cudaFuncAttributeMaxDynamicSharedMemorySize, SMEM_1P);
    cudaFuncSetAttribute((const void*)tgemm4_kernel<2>,
                         cudaFuncAttributeMaxDynamicSharedMemorySize, SMEM_1P);

    // A) LN1 + text prep + W1/W2 converts + wb2/nb2 + zero qn2
    fused_prepA_kernel<<<4817, 256>>>(vis, g1, be1, text, Wv, bv, W1, W2, Wq, bq);
    // B) G gemm + P gemms + pb
    fused_prepB_kernel<<<176, 256>>>(Wq, bq);
    // C) convert G + convert P
    fused_prepC_kernel<<<192, 256>>>();
    // D) sim + qn2 co-scheduled (640 blocks)
    fused_simqn2_kernel<<<640, 512, SMEM_SIM>>>(p_wb2);
    // E) attention epilogue + residual + LN2 -> X fp32 + Xh fp16
    attn_kernel<<<MTOT / 32, 256>>>(vis, g2, be2);
    // F) H = gelu(X @ W1 + b1) -> fp16 plane Hh
    tgemm4_kernel<1><<<dim3(HID / 128, MTOT / 256), 512, SMEM_1P>>>(
        p_Xh, p_W1h, p_W1l, b1, nullptr, nullptr, p_Hh,
        MTOT, HID, CDIM);
    // G) out = X + H @ W2 + b2
    tgemm4_kernel<2><<<dim3(CDIM / 128, MTOT / 256), 512, SMEM_1P>>>(
        p_Hh, p_W2h, p_W2l, b2, p_X, out, nullptr,
        MTOT, CDIM, HID);
}

// round 17
// speedup vs baseline: 1.0634x; 1.0634x over previous
#include <cuda_runtime.h>
#include <cuda_fp16.h>
#include <math.h>
#include <stdint.h>

// ---------------------------------------------------------------------------
// Problem constants
// ---------------------------------------------------------------------------
#define BQ    8
#define MTOT  32768
#define CDIM  512
#define TDIM  768
#define KTXT  128
#define HID   2048
#define TOPM  5
#define TEMP_INV (1.0f/0.07f)
#define LN_EPS 1e-5f
#define WSCALE 256.0f
#define WINV   (1.0f/256.0f)

// ---------------------------------------------------------------------------
// Scratch (device globals)
// ---------------------------------------------------------------------------
static __device__ uint32_t g_vh[MTOT * CDIM / 2];
static __device__ uint32_t g_vl[MTOT * CDIM / 2];
static __device__ float    g_X [MTOT * CDIM];
static __device__ uint32_t g_Xh[MTOT * CDIM / 2];
static __device__ uint32_t g_Hh[(size_t)MTOT * HID / 2];
static __device__ float    g_sim[(size_t)MTOT * KTXT];
static __device__ float    g_keyt [BQ * KTXT * TDIM];
static __device__ float    g_value[BQ * KTXT * CDIM];
static __device__ float    g_P [BQ * CDIM * KTXT];
static __device__ float    g_G [CDIM * CDIM];
static __device__ uint32_t g_Gh [CDIM * CDIM / 2];
static __device__ uint32_t g_Gl [CDIM * CDIM / 2];
static __device__ uint32_t g_Ph [BQ * KTXT * CDIM / 2];
static __device__ uint32_t g_Pl [BQ * KTXT * CDIM / 2];
static __device__ uint32_t g_W1h[(size_t)HID * CDIM / 2];
static __device__ uint32_t g_W1l[(size_t)HID * CDIM / 2];
static __device__ uint32_t g_W2h[(size_t)CDIM * HID / 2];
static __device__ uint32_t g_W2l[(size_t)CDIM * HID / 2];
static __device__ float    g_pb [BQ * KTXT];
static __device__ float    g_wb2[CDIM];
static __device__ float    g_nb2[1];
static __device__ float    g_qn2[MTOT];

// ---------------------------------------------------------------------------
// Helpers
// ---------------------------------------------------------------------------
__device__ __forceinline__ uint32_t packh2(float x, float y) {
    __half2 h = __floats2half2_rn(x, y);
    return *reinterpret_cast<uint32_t*>(&h);
}

__device__ __forceinline__ void wsplit2(float x, float y,
                                        uint32_t& hi, uint32_t& lo) {
    float sx = x * WSCALE, sy = y * WSCALE;
    __half hx = __float2half_rn(sx);
    __half hy = __float2half_rn(sy);
    float rx = sx - __half2float(hx);
    float ry = sy - __half2float(hy);
    __half2 h2 = __halves2half2(hx, hy);
    __half2 l2 = __floats2half2_rn(rx, ry);
    hi = *reinterpret_cast<uint32_t*>(&h2);
    lo = *reinterpret_cast<uint32_t*>(&l2);
}

__device__ __forceinline__ void asplit2(float x, float y,
                                        uint32_t& hi, uint32_t& lo) {
    __half hx = __float2half_rn(x);
    __half hy = __float2half_rn(y);
    float rx = x - __half2float(hx);
    float ry = y - __half2float(hy);
    __half2 h2 = __halves2half2(hx, hy);
    __half2 l2 = __floats2half2_rn(rx, ry);
    hi = *reinterpret_cast<uint32_t*>(&h2);
    lo = *reinterpret_cast<uint32_t*>(&l2);
}

__device__ __forceinline__ void mma_f16(float* c, const uint32_t* a, const uint32_t* b) {
    asm volatile(
        "mma.sync.aligned.m16n8k16.row.col.f32.f16.f16.f32 "
        "{%0,%1,%2,%3}, {%4,%5,%6,%7}, {%8,%9}, {%0,%1,%2,%3};\n"
        : "+f"(c[0]), "+f"(c[1]), "+f"(c[2]), "+f"(c[3])
        : "r"(a[0]), "r"(a[1]), "r"(a[2]), "r"(a[3]), "r"(b[0]), "r"(b[1]));
}

__device__ __forceinline__ uint32_t smem_u32(const void* p) {
    uint32_t a;
    asm("{ .reg .u64 t; cvta.to.shared.u64 t, %1; cvt.u32.u64 %0, t; }"
        : "=r"(a) : "l"(p));
    return a;
}

__device__ __forceinline__ void ldsm_x4(uint32_t& r0, uint32_t& r1,
                                        uint32_t& r2, uint32_t& r3,
                                        uint32_t addr) {
    asm volatile(
        "ldmatrix.sync.aligned.m8n8.x4.shared.b16 {%0,%1,%2,%3}, [%4];"
        : "=r"(r0), "=r"(r1), "=r"(r2), "=r"(r3) : "r"(addr));
}

__device__ __forceinline__ void cp16(uint32_t* dst_smem, const uint32_t* src) {
    uint32_t s = (uint32_t)__cvta_generic_to_shared(dst_smem);
    asm volatile("cp.async.cg.shared.global [%0], [%1], 16;\n" :: "r"(s), "l"(src));
}
__device__ __forceinline__ void cp_commit() {
    asm volatile("cp.async.commit_group;\n");
}
__device__ __forceinline__ void cp_wait1() {
    asm volatile("cp.async.wait_group 1;\n");
}

// ---------------------------------------------------------------------------
// Device bodies (prep; unchanged math)
// ---------------------------------------------------------------------------
__device__ void ln_body(const float* __restrict__ in, const float* __restrict__ g,
                        const float* __restrict__ be,
                        uint32_t* __restrict__ oh, uint32_t* __restrict__ ol, int blk)
{
    int warp = threadIdx.x >> 5, lane = threadIdx.x & 31;
    size_t row = (size_t)blk * 8 + warp;
    const float4* p = (const float4*)(in + row * CDIM);
    float4 x[4];
    float s = 0.f, s2 = 0.f;
    #pragma unroll
    for (int i = 0; i < 4; i++) {
        x[i] = p[lane + 32 * i];
        s  += x[i].x + x[i].y + x[i].z + x[i].w;
        s2 += x[i].x * x[i].x + x[i].y * x[i].y + x[i].z * x[i].z + x[i].w * x[i].w;
    }
    #pragma unroll
    for (int o = 16; o; o >>= 1) {
        s  += __shfl_xor_sync(0xffffffffu, s, o);
        s2 += __shfl_xor_sync(0xffffffffu, s2, o);
    }
    float mu  = s * (1.0f / CDIM);
    float var = s2 * (1.0f / CDIM) - mu * mu;
    float rs  = rsqrtf(var + LN_EPS);
    const float4* gp = (const float4*)g;
    const float4* bp = (const float4*)be;
    #pragma unroll
    for (int i = 0; i < 4; i++) {
        int c4 = lane + 32 * i;
        float4 gv = gp[c4], bv = bp[c4], r;
        r.x = (x[i].x - mu) * rs * gv.x + bv.x;
        r.y = (x[i].y - mu) * rs * gv.y + bv.y;
        r.z = (x[i].z - mu) * rs * gv.z + bv.z;
        r.w = (x[i].w - mu) * rs * gv.w + bv.w;
        uint2 h, l;
        asplit2(r.x, r.y, h.x, l.x);
        asplit2(r.z, r.w, h.y, l.y);
        *(uint2*)(oh + row * (CDIM / 2) + 2 * c4) = h;
        *(uint2*)(ol + row * (CDIM / 2) + 2 * c4) = l;
    }
}

__device__ void prep_text_body(const float* __restrict__ text,
                               const float* __restrict__ Wv,
                               const float* __restrict__ bv,
                               float (*ts)[TDIM], int blk)
{
    int tid = threadIdx.x, lane = tid & 31, warp = tid >> 5;
    int b  = blk >> 4;
    int kb = (blk & 15) * 8;
    const float* tb = text + ((size_t)b * KTXT + kb) * TDIM;

    #pragma unroll
    for (int i = 0; i < 24; i++) {
        int lin = tid + 256 * i;
        int r = lin / TDIM, c = lin % TDIM;
        ts[r][c] = tb[(size_t)r * TDIM + c];
    }
    __syncthreads();

    {
        int r = warp;
        float s = 0.f;
        for (int i = lane; i < TDIM; i += 32) { float v = ts[r][i]; s += v * v; }
        #pragma unroll
        for (int o = 16; o; o >>= 1) s += __shfl_xor_sync(0xffffffffu, s, o);
        float inv = 1.0f / fmaxf(sqrtf(s), 1e-12f);
        float* kr = g_keyt + ((size_t)b * KTXT + kb + r) * TDIM;
        for (int i = lane; i < TDIM; i += 32) kr[i] = ts[r][i] * inv;
    }

    float acc[8][2];
    #pragma unroll
    for (int r = 0; r < 8; r++) { acc[r][0] = 0.f; acc[r][1] = 0.f; }
    int c0 = tid, c1 = tid + 256;
    for (int t = 0; t < TDIM; t++) {
        float w0 = Wv[(size_t)t * CDIM + c0];
        float w1 = Wv[(size_t)t * CDIM + c1];
        #pragma unroll
        for (int r = 0; r < 8; r++) {
            float tv = ts[r][t];
            acc[r][0] += tv * w0;
            acc[r][1] += tv * w1;
        }
    }
    float bb0 = bv[c0], bb1 = bv[c1];
    #pragma unroll
    for (int r = 0; r < 8; r++) {
        float* vr = g_value + ((size_t)b * KTXT + kb + r) * CDIM;
        vr[c0] = acc[r][0] + bb0;
        vr[c1] = acc[r][1] + bb1;
    }
}

__device__ void convert_body(const float* __restrict__ in,
                             uint32_t* __restrict__ oh, uint32_t* __restrict__ ol,
                             int Kd, int N, int bx, int by, int bz,
                             size_t inStride, size_t outStride, float (*t)[65])
{
    int k0 = by * 64, n0 = bx * 64;
    const float* inb = in + (size_t)bz * inStride;
    int tid = threadIdx.x;
    #pragma unroll
    for (int i = 0; i < 16; i++) {
        int lin = tid + 256 * i;
        int r = lin >> 6, c = lin & 63;
        t[r][c] = inb[(size_t)(k0 + r) * N + n0 + c];
    }
    __syncthreads();
    int K2 = Kd >> 1;
    #pragma unroll
    for (int i = 0; i < 8; i++) {
        int lin = tid + 256 * i;
        int n = lin >> 5, kp = lin & 31;
        uint32_t h, l;
        wsplit2(t[2 * kp][n], t[2 * kp + 1][n], h, l);
        size_t o = (size_t)bz * outStride + (size_t)(n0 + n) * K2 + (k0 >> 1) + kp;
        oh[o] = h;  ol[o] = l;
    }
}

__device__ void wb2_body(const float* __restrict__ Wq,
                         const float* __restrict__ bq, int gw2)
{
    if (gw2 > 512) return;
    int lane = threadIdx.x & 31;
    const float4* bp = (const float4*)bq;
    float s = 0.f;
    if (gw2 < 512) {
        const float4* wr = (const float4*)(Wq + (size_t)gw2 * TDIM);
        #pragma unroll
        for (int i = 0; i < 6; i++) {
            float4 a = wr[lane + 32 * i], d = bp[lane + 32 * i];
            s += a.x * d.x + a.y * d.y + a.z * d.z + a.w * d.w;
        }
        #pragma unroll
        for (int o = 16; o; o >>= 1) s += __shfl_xor_sync(0xffffffffu, s, o);
        if (!lane) g_wb2[gw2] = 2.0f * s;
    } else {
        #pragma unroll
        for (int i = 0; i < 6; i++) {
            float4 a = bp[lane + 32 * i];
            s += a.x * a.x + a.y * a.y + a.z * a.z + a.w * a.w;
        }
        #pragma unroll
        for (int o = 16; o; o >>= 1) s += __shfl_xor_sync(0xffffffffu, s, o);
        if (!lane) g_nb2[0] = s;
    }
}

__device__ void pb_body(const float* __restrict__ bq, int gw)
{
    if (gw >= 1024) return;
    int lane = threadIdx.x & 31;
    const float4* bp = (const float4*)bq;
    const float4* kr = (const float4*)(g_keyt + (size_t)gw * TDIM);
    float s = 0.f;
    #pragma unroll
    for (int i = 0; i < 6; i++) {
        float4 a = kr[lane + 32 * i], c = bp[lane + 32 * i];
        s += a.x * c.x + a.y * c.y + a.z * c.z + a.w * c.w;
    }
    #pragma unroll
    for (int o = 16; o; o >>= 1) s += __shfl_xor_sync(0xffffffffu, s, o);
    if (!lane) g_pb[gw] = s;
}

__device__ void sgemm_body(const float* __restrict__ A, const float* __restrict__ B2,
                           float* __restrict__ C, int Kd, int N, int bn, int bm,
                           float (*As)[128], float (*Bs)[128])
{
    int tid = threadIdx.x;
    int tx = tid & 15, ty = tid >> 4;
    const float* Ab = A  + (size_t)bm * 128 * Kd;
    const float* Bb = B2 + (size_t)bn * 128 * Kd;
    int l_r = tid >> 1, l_k = (tid & 1) * 4;

    float acc[8][8];
    #pragma unroll
    for (int i = 0; i < 8; i++)
        #pragma unroll
        for (int j = 0; j < 8; j++) acc[i][j] = 0.f;

    for (int k0 = 0; k0 < Kd; k0 += 8) {
        float4 av = *(const float4*)(Ab + (size_t)l_r * Kd + k0 + l_k);
        As[l_k + 0][l_r] = av.x;
        As[l_k + 1][l_r] = av.y;
        As[l_k + 2][l_r] = av.z;
        As[l_k + 3][l_r] = av.w;
        float4 bv = *(const float4*)(Bb + (size_t)l_r * Kd + k0 + l_k);
        Bs[l_k + 0][l_r] = bv.x;
        Bs[l_k + 1][l_r] = bv.y;
        Bs[l_k + 2][l_r] = bv.z;
        Bs[l_k + 3][l_r] = bv.w;
        __syncthreads();
        #pragma unroll
        for (int k = 0; k < 8; k++) {
            float ar[8], br[8];
            #pragma unroll
            for (int i = 0; i < 4; i++) {
                ar[i]     = As[k][ty * 4 + i];
                ar[4 + i] = As[k][64 + ty * 4 + i];
                br[i]     = Bs[k][tx * 4 + i];
                br[4 + i] = Bs[k][64 + tx * 4 + i];
            }
            #pragma unroll
            for (int i = 0; i < 8; i++)
                #pragma unroll
                for (int j = 0; j < 8; j++) acc[i][j] += ar[i] * br[j];
        }
        __syncthreads();
    }

    #pragma unroll
    for (int gi = 0; gi < 2; gi++)
        #pragma unroll
        for (int ii = 0; ii < 4; ii++) {
            int r = bm * 128 + gi * 64 + ty * 4 + ii;
            #pragma unroll
            for (int gj = 0; gj < 2; gj++) {
                int cb = bn * 128 + gj * 64 + tx * 4;
                float4 o;
                o.x = acc[gi * 4 + ii][gj * 4 + 0];
                o.y = acc[gi * 4 + ii][gj * 4 + 1];
                o.z = acc[gi * 4 + ii][gj * 4 + 2];
                o.w = acc[gi * 4 + ii][gj * 4 + 3];
                *(float4*)(C + (size_t)r * N + cb) = o;
            }
        }
}

// ---------------------------------------------------------------------------
// fp16 tensor-core GEMM body: 128x128 tile, 256 threads (8 warps, 2m x 4n),
// 2-stage double buffer -> 32K regs + <=80KB smem = 2 blocks/SM (latency hiding).
// MODE 0: sim -> Out fp32, per-batch B (batch = bm>>5)
// MODE 1: gelu(acc/256+bias) -> fp16 plane Oh
// MODE 2: acc/256+bias+Res -> Out fp32
// MODE 3: qn2[r] += sum_c (acc/256)*(h+2l) + bias*(h+l)
// ---------------------------------------------------------------------------
#define A_PLANE 2560          // 128 rows * 20 u32
#define B_PLANE 2560

template <int MODE, int AP, int BP>
__device__ void tg_body(
    const uint32_t* __restrict__ Ah, const uint32_t* __restrict__ Al,
    const uint32_t* __restrict__ Bh, const uint32_t* __restrict__ Bl,
    const float* __restrict__ bias, const float* __restrict__ Res,
    float* __restrict__ Out, uint32_t* __restrict__ Oh,
    int M, int N, int Kd, int bn, int bm, uint32_t* sm)
{
    const int STG = AP * A_PLANE + BP * B_PLANE;
    uint32_t sbase = smem_u32(sm);
    int K2 = Kd >> 1;
    int tid = threadIdx.x, lane = tid & 31, warp = tid >> 5;
    int g  = lane >> 2, tg = lane & 3;
    int wm = warp >> 2, wn = warp & 3;        // 2m x 4n
    int m0 = wm * 64,  n0 = wn * 32;

    const uint32_t* AhB = Ah + (size_t)bm * 128 * K2;
    const uint32_t* AlB = (AP == 2) ? Al + (size_t)bm * 128 * K2 : nullptr;
    size_t bofs = (size_t)bn * 128 * K2;
    if (MODE == 0) bofs += (size_t)(bm >> 5) * KTXT * K2;   // per-batch B
    const uint32_t* BhB = Bh + bofs;
    const uint32_t* BlB = (BP == 2) ? Bl + bofs : nullptr;

    uint32_t a_ld = (uint32_t)((m0 + (lane & 7) + ((lane >> 3) & 1) * 8) * 20
                               + ((lane >> 4) & 1) * 4) * 4;
    uint32_t b_ld = (uint32_t)((n0 + (lane & 7) + ((lane >> 4) & 1) * 8) * 20
                               + ((lane >> 3) & 1) * 4) * 4;

    float acc[4][4][4];
    #pragma unroll
    for (int mi = 0; mi < 4; mi++)
        #pragma unroll
        for (int ni = 0; ni < 4; ni++)
            #pragma unroll
            for (int r = 0; r < 4; r++) acc[mi][ni][r] = 0.f;

    int nT = K2 / 16;
    const int AOFF = AP * A_PLANE;

    // loader: 512 chunks per plane (128 rows x 4 kb), 256 threads -> 2 each
    // prologue: stage tiles 0 and 1
    #pragma unroll
    for (int pf = 0; pf < 2; pf++) {
        uint32_t* st = sm + pf * STG;
        int kp0 = pf * 16;
        #pragma unroll
        for (int c = 0; c < 2; c++) {
            int idx = tid + 256 * c;
            int row = idx >> 2, kb = (idx & 3) * 4;
            size_t go = (size_t)row * K2 + kp0 + kb;
            int so = row * 20 + kb;
            cp16(st + so, AhB + go);
            if (AP == 2) cp16(st + A_PLANE + so, AlB + go);
            cp16(st + AOFF + so, BhB + go);
            if (BP == 2) cp16(st + AOFF + B_PLANE + so, BlB + go);
        }
        cp_commit();
    }

    for (int t = 0; t < nT; t++) {
        cp_wait1();
        __syncthreads();
        uint32_t stb = sbase + (uint32_t)((t & 1) * STG * 4);

        #pragma unroll
        for (int ks = 0; ks < 2; ks++) {
            uint32_t ksoff = (uint32_t)(ks * 32);
            uint32_t a[4][4], al[4][4], bh[4][2], bl[4][2];
            #pragma unroll
            for (int mi = 0; mi < 4; mi++) {
                uint32_t ao = stb + a_ld + ksoff + (uint32_t)(mi * 16 * 80);
                ldsm_x4(a[mi][0], a[mi][1], a[mi][2], a[mi][3], ao);
                if (AP == 2)
                    ldsm_x4(al[mi][0], al[mi][1], al[mi][2], al[mi][3],
                            ao + A_PLANE * 4);
            }
            #pragma unroll
            for (int p = 0; p < 2; p++) {
                uint32_t bo = stb + AOFF * 4 + b_ld + ksoff + (uint32_t)(p * 16 * 80);
                ldsm_x4(bh[2 * p][0], bh[2 * p][1], bh[2 * p + 1][0], bh[2 * p + 1][1], bo);
                if (BP == 2)
                    ldsm_x4(bl[2 * p][0], bl[2 * p][1], bl[2 * p + 1][0], bl[2 * p + 1][1],
                            bo + B_PLANE * 4);
            }
            #pragma unroll
            for (int mi = 0; mi < 4; mi++)
                #pragma unroll
                for (int ni = 0; ni < 4; ni++) {
                    mma_f16(acc[mi][ni], a[mi], bh[ni]);
                    if (BP == 2) mma_f16(acc[mi][ni], a[mi], bl[ni]);
                    if (AP == 2) mma_f16(acc[mi][ni], al[mi], bh[ni]);
                }
        }
        __syncthreads();
        if (t + 2 < nT) {
            uint32_t* dst = sm + (t & 1) * STG;
            int kp0 = (t + 2) * 16;
            #pragma unroll
            for (int c = 0; c < 2; c++) {
                int idx = tid + 256 * c;
                int row = idx >> 2, kb = (idx & 3) * 4;
                size_t go = (size_t)row * K2 + kp0 + kb;
                int so = row * 20 + kb;
                cp16(dst + so, AhB + go);
                if (AP == 2) cp16(dst + A_PLANE + so, AlB + go);
                cp16(dst + AOFF + so, BhB + go);
                if (BP == 2) cp16(dst + AOFF + B_PLANE + so, BlB + go);
            }
        }
        cp_commit();
    }

    if (MODE == 3) {
        #pragma unroll
        for (int mi = 0; mi < 4; mi++)
            #pragma unroll
            for (int half = 0; half < 2; half++) {
                int r = bm * 128 + m0 + mi * 16 + g + half * 8;
                float part = 0.f;
                #pragma unroll
                for (int ni = 0; ni < 4; ni++) {
                    int c = bn * 128 + n0 + ni * 8 + 2 * tg;
                    uint32_t hu = Ah[(size_t)r * (N >> 1) + (c >> 1)];
                    uint32_t lu = Al[(size_t)r * (N >> 1) + (c >> 1)];
                    __half2 h2 = *reinterpret_cast<__half2*>(&hu);
                    __half2 l2 = *reinterpret_cast<__half2*>(&lu);
                    float h0 = __half2float(__low2half(h2));
                    float h1 = __half2float(__high2half(h2));
                    float l0 = __half2float(__low2half(l2));
                    float l1 = __half2float(__high2half(l2));
                    float z0 = acc[mi][ni][half * 2 + 0] * WINV;
                    float z1 = acc[mi][ni][half * 2 + 1] * WINV;
                    part += z0 * (h0 + 2.0f * l0) + bias[c]     * (h0 + l0);
                    part += z1 * (h1 + 2.0f * l1) + bias[c + 1] * (h1 + l1);
                }
                part += __shfl_xor_sync(0xffffffffu, part, 1);
                part += __shfl_xor_sync(0xffffffffu, part, 2);
                if (tg == 0) atomicAdd(&g_qn2[r], part);
            }
        return;
    }

    #pragma unroll
    for (int mi = 0; mi < 4; mi++)
        #pragma unroll
        for (int half = 0; half < 2; half++) {
            int r = bm * 128 + m0 + mi * 16 + g + half * 8;
            #pragma unroll
            for (int ni = 0; ni < 4; ni++) {
                int c = bn * 128 + n0 + ni * 8 + 2 * tg;
                float v0 = acc[mi][ni][half * 2 + 0] * WINV;
                float v1 = acc[mi][ni][half * 2 + 1] * WINV;
                if (MODE == 0) {
                    float2 ov = { v0, v1 };
                    *(float2*)(Out + (size_t)r * KTXT + c) = ov;
                } else if (MODE == 1) {
                    v0 += bias[c];  v1 += bias[c + 1];
                    v0 = v0 * normcdff(v0);
                    v1 = v1 * normcdff(v1);
                    Oh[(size_t)r * (N >> 1) + (c >> 1)] = packh2(v0, v1);
                } else {
                    v0 += bias[c]     + Res[(size_t)r * N + c];
                    v1 += bias[c + 1] + Res[(size_t)r * N + c + 1];
                    float2 ov = { v0, v1 };
                    *(float2*)(Out + (size_t)r * N + c) = ov;
                }
            }
        }
}

// Thin wrappers for the FFN GEMMs (256 threads)
template <int MODE>
__global__ __launch_bounds__(256) void tgemm4_kernel(
    const uint32_t* __restrict__ Ah,
    const uint32_t* __restrict__ Bh, const uint32_t* __restrict__ Bl,
    const float* __restrict__ bias, const float* __restrict__ Res,
    float* __restrict__ Out, uint32_t* __restrict__ Oh,
    int M, int N, int Kd)
{
    extern __shared__ uint32_t sm[];
    tg_body<MODE, 1, 1>(Ah, nullptr, Bh, Bl, bias, Res, Out, Oh,
                        M, N, Kd, blockIdx.x, blockIdx.y, sm);
}

// Merged sim + qn2: blocks [0,256) sim<0,2,2>, [256,1280) qn2<3,1,1>
__global__ __launch_bounds__(256) void fused_simqn2_kernel(
    const float* __restrict__ wb2)
{
    extern __shared__ uint32_t sm[];
    int j = blockIdx.x;
    if (j < 256) {
        tg_body<0, 2, 2>(g_vh, g_vl, g_Ph, g_Pl, nullptr, nullptr,
                         g_sim, nullptr, MTOT, KTXT, CDIM, 0, j, sm);
    } else {
        int jj = j - 256;
        tg_body<3, 1, 1>(g_vh, g_vl, g_Gh, nullptr, wb2, nullptr,
                         nullptr, nullptr, MTOT, CDIM, CDIM,
                         jj >> 8, jj & 255, sm);
    }
}

// ---------------------------------------------------------------------------
// Fused prep launch A
// ---------------------------------------------------------------------------
__global__ __launch_bounds__(256) void fused_prepA_kernel(
    const float* __restrict__ vis, const float* __restrict__ g1,
    const float* __restrict__ be1,
    const float* __restrict__ text, const float* __restrict__ Wv,
    const float* __restrict__ bv,
    const float* __restrict__ W1, const float* __restrict__ W2,
    const float* __restrict__ Wq, const float* __restrict__ bq)
{
    __shared__ __align__(16) char sbuf[24576];
    int j = blockIdx.x;
    if (j < 4096) {
        ln_body(vis, g1, be1, g_vh, g_vl, j);
    } else if (j < 4224) {
        prep_text_body(text, Wv, bv, (float(*)[TDIM])sbuf, j - 4096);
    } else if (j < 4480) {
        int jj = j - 4224;
        convert_body(W1, g_W1h, g_W1l, CDIM, HID, jj & 31, jj >> 5, 0, 0, 0,
                     (float(*)[65])sbuf);
    } else if (j < 4736) {
        int jj = j - 4480;
        convert_body(W2, g_W2h, g_W2l, HID, CDIM, jj & 7, jj >> 3, 0, 0, 0,
                     (float(*)[65])sbuf);
    } else if (j < 4801) {
        int gw2 = (j - 4736) * 8 + (threadIdx.x >> 5);
        wb2_body(Wq, bq, gw2);
    } else {
        int base = (j - 4801) * 2048 + threadIdx.x * 8;
        float4 z = { 0.f, 0.f, 0.f, 0.f };
        *(float4*)(g_qn2 + base)     = z;
        *(float4*)(g_qn2 + base + 4) = z;
    }
}

// ---------------------------------------------------------------------------
// Fused prep launch B: G gemm | P gemms | pb
// ---------------------------------------------------------------------------
__global__ __launch_bounds__(256) void fused_prepB_kernel(
    const float* __restrict__ Wq, const float* __restrict__ bq)
{
    __shared__ __align__(16) float As[8][128];
    __shared__ float Bs[8][128];
    int j = blockIdx.x;
    if (j < 16) {
        sgemm_body(Wq, Wq, g_G, TDIM, CDIM, j & 3, j >> 2, As, Bs);
    } else if (j < 48) {
        int jj = j - 16;
        int bz = jj >> 2, bm = jj & 3;
        sgemm_body(Wq, g_keyt + (size_t)bz * KTXT * TDIM,
                   g_P + (size_t)bz * CDIM * KTXT,
                   TDIM, KTXT, 0, bm, As, Bs);
    } else {
        int gw = (j - 48) * 8 + (threadIdx.x >> 5);
        pb_body(bq, gw);
    }
}

// ---------------------------------------------------------------------------
// Fused prep launch C: convert G | convert P
// ---------------------------------------------------------------------------
__global__ __launch_bounds__(256) void fused_prepC_kernel()
{
    __shared__ __align__(16) float t[64][65];
    int j = blockIdx.x;
    if (j < 64) {
        convert_body(g_G, g_Gh, g_Gl, CDIM, CDIM, j & 7, j >> 3, 0, 0, 0, t);
    } else {
        int jj = j - 64;
        convert_body(g_P, g_Ph, g_Pl, CDIM, KTXT, jj & 1, (jj >> 1) & 7, jj >> 4,
                     (size_t)CDIM * KTXT, (size_t)KTXT * CDIM / 2, t);
    }
}

// ---------------------------------------------------------------------------
// Attention epilogue (unchanged)
// ---------------------------------------------------------------------------
__global__ __launch_bounds__(256) void attn_kernel(
    const float* __restrict__ resid, const float* __restrict__ g2,
    const float* __restrict__ be2)
{
    __shared__ float invn[32];
    __shared__ float pb_s[KTXT];
    int tid = threadIdx.x, lane = tid & 31, warp = tid >> 5;
    int t0 = blockIdx.x * 32;
    int b  = t0 >> 12;

    if (tid < 32) {
        float qn2 = g_qn2[t0 + tid] + g_nb2[0];
        float n = sqrtf(fmaxf(qn2, 0.f));
        invn[tid] = 1.0f / fmaxf(n, 1e-12f);
    }
    if (tid < KTXT) pb_s[tid] = g_pb[b * KTXT + tid];
    __syncthreads();

    for (int rr = 0; rr < 4; rr++) {
        int row = warp * 4 + rr;
        float sc = invn[row];
        const float* sp = g_sim + (size_t)(t0 + row) * KTXT;
        float tv[4];
        #pragma unroll
        for (int j = 0; j < 4; j++) {
            int col = lane + 32 * j;
            tv[j] = (sp[col] + pb_s[col]) * sc;
        }

        float mval[TOPM]; int midx[TOPM];
        #pragma unroll
        for (int it = 0; it < TOPM; it++) {
            float lm = tv[0]; int lj = 0;
            #pragma unroll
            for (int j = 1; j < 4; j++) if (tv[j] > lm) { lm = tv[j]; lj = j; }
            int li = lane + 32 * lj;
            #pragma unroll
            for (int o = 16; o; o >>= 1) {
                float ov = __shfl_xor_sync(0xffffffffu, lm, o);
                int   oi = __shfl_xor_sync(0xffffffffu, li, o);
                if (ov > lm || (ov == lm && oi < li)) { lm = ov; li = oi; }
            }
            mval[it] = lm; midx[it] = li;
            if ((li & 31) == lane) tv[li >> 5] = -INFINITY;
        }

        float p[TOPM], psum = 0.f;
        #pragma unroll
        for (int it = 0; it < TOPM; it++) {
            p[it] = expf((mval[it] - mval[0]) * TEMP_INV);
            psum += p[it];
        }
        float rnorm = 1.0f / psum;

        float f[16];
        #pragma unroll
        for (int i = 0; i < 16; i++) f[i] = 0.f;
        const float* Vb = g_value + (size_t)b * KTXT * CDIM;
        #pragma unroll
        for (int it = 0; it < TOPM; it++) {
            const float4* vr = (const float4*)(Vb + (size_t)midx[it] * CDIM + lane * 16);
            float a_ = p[it] * rnorm;
            #pragma unroll
            for (int j = 0; j < 4; j++) {
                float4 v = vr[j];
                f[4 * j + 0] += a_ * v.x;
                f[4 * j + 1] += a_ * v.y;
                f[4 * j + 2] += a_ * v.z;
                f[4 * j + 3] += a_ * v.w;
            }
        }

        const float4* rp = (const float4*)(resid + (size_t)(t0 + row) * CDIM + lane * 16);
        float s = 0.f, s2 = 0.f;
        #pragma unroll
        for (int j = 0; j < 4; j++) {
            float4 v = rp[j];
            f[4 * j + 0] += v.x;  f[4 * j + 1] += v.y;
            f[4 * j + 2] += v.z;  f[4 * j + 3] += v.w;
        }
        #pragma unroll
        for (int i = 0; i < 16; i++) { s += f[i]; s2 += f[i] * f[i]; }
        #pragma unroll
        for (int o = 16; o; o >>= 1) {
            s  += __shfl_xor_sync(0xffffffffu, s, o);
            s2 += __shfl_xor_sync(0xffffffffu, s2, o);
        }
        float mu  = s * (1.0f / CDIM);
        float var = s2 * (1.0f / CDIM) - mu * mu;
        float rstd = rsqrtf(var + LN_EPS);

        size_t rbase = (size_t)(t0 + row);
        float*    xp = g_X  + rbase * CDIM + lane * 16;
        uint32_t* xh = g_Xh + rbase * (CDIM / 2) + lane * 8;
        #pragma unroll
        for (int j = 0; j < 4; j++) {
            int c = lane * 16 + 4 * j;
            float4 o;
            o.x = (f[4 * j + 0] - mu) * rstd * g2[c + 0] + be2[c + 0];
            o.y = (f[4 * j + 1] - mu) * rstd * g2[c + 1] + be2[c + 1];
            o.z = (f[4 * j + 2] - mu) * rstd * g2[c + 2] + be2[c + 2];
            o.w = (f[4 * j + 3] - mu) * rstd * g2[c + 3] + be2[c + 3];
            *(float4*)(xp + 4 * j) = o;
            uint2 h;
            h.x = packh2(o.x, o.y);
            h.y = packh2(o.z, o.w);
            *(uint2*)(xh + 2 * j) = h;
        }
    }
}

// ---------------------------------------------------------------------------
// Launch
// ---------------------------------------------------------------------------
extern "C" void kernel_launch(void* const* d_in, const int* in_sizes, int n_in,
                              void* d_out, int out_size)
{
    const float* vis  = (const float*)d_in[0];
    const float* text = (const float*)d_in[1];
    const float* Wq   = (const float*)d_in[2];
    const float* bq   = (const float*)d_in[3];
    const float* Wv   = (const float*)d_in[4];
    const float* bv   = (const float*)d_in[5];
    const float* W1   = (const float*)d_in[6];
    const float* b1   = (const float*)d_in[7];
    const float* W2   = (const float*)d_in[8];
    const float* b2   = (const float*)d_in[9];
    const float* g1   = (const float*)d_in[10];
    const float* be1  = (const float*)d_in[11];
    const float* g2   = (const float*)d_in[12];
    const float* be2  = (const float*)d_in[13];
    float* out = (float*)d_out;

    float *p_X, *p_wb2;
    uint32_t *p_Xh, *p_Hh, *p_W1h, *p_W1l, *p_W2h, *p_W2l;
    cudaGetSymbolAddress((void**)&p_X,     g_X);
    cudaGetSymbolAddress((void**)&p_wb2,   g_wb2);
    cudaGetSymbolAddress((void**)&p_Xh,    g_Xh);
    cudaGetSymbolAddress((void**)&p_Hh,    g_Hh);
    cudaGetSymbolAddress((void**)&p_W1h,   g_W1h);
    cudaGetSymbolAddress((void**)&p_W1l,   g_W1l);
    cudaGetSymbolAddress((void**)&p_W2h,   g_W2h);
    cudaGetSymbolAddress((void**)&p_W2l,   g_W2l);

    const int SMEM_1P  = 2 * (1 * A_PLANE + 1 * B_PLANE) * 4;   // 40960
    const int SMEM_SIM = 2 * (2 * A_PLANE + 2 * B_PLANE) * 4;   // 81920
    cudaFuncSetAttribute((const void*)fused_simqn2_kernel,
                         cudaFuncAttributeMaxDynamicSharedMemorySize, SMEM_SIM);
    cudaFuncSetAttribute((const void*)tgemm4_kernel<1>,
                         cudaFuncAttributeMaxDynamicSharedMemorySize, SMEM_1P);
    cudaFuncSetAttribute((const void*)tgemm4_kernel<2>,
                         cudaFuncAttributeMaxDynamicSharedMemorySize, SMEM_1P);

    // A) LN1 + text prep + W1/W2 converts + wb2/nb2 + zero qn2
    fused_prepA_kernel<<<4817, 256>>>(vis, g1, be1, text, Wv, bv, W1, W2, Wq, bq);
    // B) G gemm + P gemms + pb
    fused_prepB_kernel<<<176, 256>>>(Wq, bq);
    // C) convert G + convert P
    fused_prepC_kernel<<<192, 256>>>();
    // D) sim + qn2 co-scheduled (1280 blocks, 2 blocks/SM)
    fused_simqn2_kernel<<<1280, 256, SMEM_SIM>>>(p_wb2);
    // E) attention epilogue + residual + LN2 -> X fp32 + Xh fp16
    attn_kernel<<<MTOT / 32, 256>>>(vis, g2, be2);
    // F) H = gelu(X @ W1 + b1) -> fp16 plane Hh
    tgemm4_kernel<1><<<dim3(HID / 128, MTOT / 128), 256, SMEM_1P>>>(
        p_Xh, p_W1h, p_W1l, b1, nullptr, nullptr, p_Hh,
        MTOT, HID, CDIM);
    // G) out = X + H @ W2 + b2
    tgemm4_kernel<2><<<dim3(CDIM / 128, MTOT / 128), 256, SMEM_1P>>>(
        p_Hh, p_W2h, p_W2l, b2, p_X, out, nullptr,
        MTOT, CDIM, HID);
}